// round 11
// baseline (speedup 1.0000x reference)
#include <cuda_runtime.h>
#include <cuda_fp16.h>
#include <cstdint>
#include <math.h>

#define Bb 4
#define Ss 1024
#define Tt 1024
#define Dd 1024
#define Hh 16
#define DHh 2048
#define SP 1032   // S + 8 padding rows for conv1

// ======================= scratch ============================================
__device__ __half g16_h   [(size_t)Bb*Ss*Dd];
__device__ __half g16_qkv [(size_t)Bb*Ss*3072];
__device__ __half g16_q2  [(size_t)Bb*Ss*Dd];
__device__ __half g16_kv2 [(size_t)Bb*Ss*2048];
__device__ __half g16_ao  [(size_t)Bb*Ss*Dd];
__device__ __half g16_xa  [(size_t)Bb*Tt*Dd];
__device__ __half g16_xpad[(size_t)Bb*SP*Dd];
__device__ __half g16_y   [(size_t)Bb*Ss*DHh];
__device__ __half g16_wp  [(size_t)8*Dd*Dd];
__device__ __half g16_wc1 [(size_t)DHh*9*Dd];
__device__ __half g16_wc2 [(size_t)Dd*DHh];
__device__ float  g_x1 [Bb*Ss*Dd];
__device__ float  g_x2 [Bb*Ss*Dd];
__device__ float  g_z  [Bb*Ss*Dd];
__device__ float  g_bqkv[3072];
__device__ float  g_bkv [2048];
__device__ float  g_attn[(size_t)Bb*Hh*Ss*Tt];   // fallback if attn not in d_out

// ======================= small PTX helpers ==================================
__device__ __forceinline__ void cpa16(void* s, const void* g) {
    uint32_t sa = (uint32_t)__cvta_generic_to_shared(s);
    asm volatile("cp.async.cg.shared.global [%0], [%1], 16;"
                 :: "r"(sa), "l"(__cvta_generic_to_global(g)));
}
#define CP_COMMIT() asm volatile("cp.async.commit_group;" ::: "memory")
#define CP_WAIT1()  asm volatile("cp.async.wait_group 1;" ::: "memory")

__device__ __forceinline__ void ldmx4(uint32_t* r, const void* p) {
    uint32_t a = (uint32_t)__cvta_generic_to_shared(p);
    asm volatile("ldmatrix.sync.aligned.m8n8.x4.shared.b16 {%0,%1,%2,%3}, [%4];"
                 : "=r"(r[0]), "=r"(r[1]), "=r"(r[2]), "=r"(r[3]) : "r"(a));
}
__device__ __forceinline__ void ldmx4t(uint32_t* r, const void* p) {
    uint32_t a = (uint32_t)__cvta_generic_to_shared(p);
    asm volatile("ldmatrix.sync.aligned.m8n8.x4.trans.shared.b16 {%0,%1,%2,%3}, [%4];"
                 : "=r"(r[0]), "=r"(r[1]), "=r"(r[2]), "=r"(r[3]) : "r"(a));
}
__device__ __forceinline__ void mma16816(float* c, const uint32_t* a, const uint32_t* b) {
    asm volatile("mma.sync.aligned.m16n8k16.row.col.f32.f16.f16.f32 "
                 "{%0,%1,%2,%3}, {%4,%5,%6,%7}, {%8,%9}, {%0,%1,%2,%3};"
                 : "+f"(c[0]), "+f"(c[1]), "+f"(c[2]), "+f"(c[3])
                 : "r"(a[0]), "r"(a[1]), "r"(a[2]), "r"(a[3]),
                   "r"(b[0]), "r"(b[1]));
}
__device__ __forceinline__ uint32_t packh2(float a, float b) {
    __half2 h = __floats2half2_rn(a, b);
    return *(uint32_t*)&h;
}

// ======================= LayerNorm ==========================================
template<bool OUTH>
__global__ void ln_kernel(const float* __restrict__ x,
                          const float* __restrict__ gg,
                          const float* __restrict__ bb,
                          void* __restrict__ outv)
{
    __shared__ float s1[8], s2[8], mv[2];
    long row = blockIdx.x;
    int t = threadIdx.x;
    float4 v = ((const float4*)(x + row * Dd))[t];
    float s = v.x + v.y + v.z + v.w;
    float q = v.x*v.x + v.y*v.y + v.z*v.z + v.w*v.w;
    #pragma unroll
    for (int o = 16; o > 0; o >>= 1) {
        s += __shfl_down_sync(0xffffffffu, s, o);
        q += __shfl_down_sync(0xffffffffu, q, o);
    }
    if ((t & 31) == 0) { s1[t >> 5] = s; s2[t >> 5] = q; }
    __syncthreads();
    if (t == 0) {
        float a = 0.f, c = 0.f;
        #pragma unroll
        for (int i = 0; i < 8; i++) { a += s1[i]; c += s2[i]; }
        float mu  = a * (1.0f / Dd);
        float var = c * (1.0f / Dd) - mu * mu;
        mv[0] = mu; mv[1] = rsqrtf(var + 1e-5f);
    }
    __syncthreads();
    float mu = mv[0], rs = mv[1];
    float4 gv = ((const float4*)gg)[t];
    float4 bv = ((const float4*)bb)[t];
    float o0 = (v.x - mu) * rs * gv.x + bv.x;
    float o1 = (v.y - mu) * rs * gv.y + bv.y;
    float o2 = (v.z - mu) * rs * gv.z + bv.z;
    float o3 = (v.w - mu) * rs * gv.w + bv.w;
    if (OUTH) {
        __align__(8) __half hh[4] = {__float2half(o0), __float2half(o1),
                                     __float2half(o2), __float2half(o3)};
        *(uint2*)((__half*)outv + row * Dd + t * 4) = *(uint2*)hh;
    } else {
        ((float4*)((float*)outv + row * Dd))[t] = make_float4(o0, o1, o2, o3);
    }
}

// ========== Fused QK^T + softmax + P@V (flash-style, 32 q-rows/CTA) =========
// Q rows stride ldq (head offset applied here), K rows stride ldkv, V = K+1024.
// Logits *0.125. Outputs: attn fp32 [bh][S][T], O fp16 into ao[b][s][h*64+dh].
__global__ void __launch_bounds__(256)
qk_sm_av(const __half* __restrict__ qp, int ldq,
         const __half* __restrict__ kvp, int ldkv,
         float* __restrict__ attn, __half* __restrict__ ao)
{
    extern __shared__ char dsm[];
    __half (*Qs)[72] = reinterpret_cast<__half(*)[72]>(dsm);                  // 32x72
    __half (*KV)[128][72] = reinterpret_cast<__half(*)[128][72]>(dsm + 4608); // 3 stages
    float* redm = reinterpret_cast<float*>(dsm + 60416 - 512);                // 32x4
    float* reds = redm + 128;                                                 // 32x4
    float* Po   = reinterpret_cast<float*>(dsm + 60416);                      // 4x32x64

    const int bh = blockIdx.y;
    const int b = bh >> 4, h = bh & 15;
    const __half* Q = qp + (long)b * Ss * ldq + (long)h * 64;
    const __half* K = kvp + (long)b * Ss * ldkv + (long)h * 64;
    const __half* V = K + 1024;
    const int m0 = blockIdx.x * 32;
    const int t = threadIdx.x, lane = t & 31, w = t >> 5;
    const int g = w >> 2, wc = w & 3;

    {
        int r = t >> 3, cc = (t & 7) * 8;
        cpa16(&Qs[r][cc], Q + (long)(m0 + r) * ldq + cc);
    }
    const int ldr = t >> 1, ldc0 = (t & 1) * 32;
    auto loadT = [&](const __half* src0, int buf, int ch) {
        const __half* src = src0 + (long)(ch * 128 + ldr) * ldkv + ldc0;
        cpa16(&KV[buf][ldr][ldc0],      src);
        cpa16(&KV[buf][ldr][ldc0 + 8],  src + 8);
        cpa16(&KV[buf][ldr][ldc0 + 16], src + 16);
        cpa16(&KV[buf][ldr][ldc0 + 24], src + 24);
    };
    loadT(K, 0, 0); CP_COMMIT();
    loadT(K, 1, 1); CP_COMMIT();

    float acc[8][4][4];
    #pragma unroll
    for (int i = 0; i < 8; i++)
        #pragma unroll
        for (int j = 0; j < 4; j++)
            #pragma unroll
            for (int p = 0; p < 4; p++) acc[i][j][p] = 0.f;

    const int lr16 = lane & 15, lk8 = (lane >> 4) * 8;
    for (int ch = 0; ch < 8; ch++) {
        CP_WAIT1();
        __syncthreads();
        if (ch + 2 < 8) loadT(K, (ch + 2) % 3, ch + 2);
        CP_COMMIT();
        const int buf = ch % 3;
        #pragma unroll
        for (int ks = 0; ks < 4; ks++) {
            uint32_t a[4];
            ldmx4(a, &Qs[g * 16 + lr16][ks * 16 + lk8]);
            uint32_t bf[4][2];
            #pragma unroll
            for (int p = 0; p < 2; p++) {
                uint32_t mrr[4];
                ldmx4(mrr, &KV[buf][wc * 32 + p * 16 + lr16][ks * 16 + lk8]);
                bf[2*p][0]   = mrr[0]; bf[2*p][1]   = mrr[2];
                bf[2*p+1][0] = mrr[1]; bf[2*p+1][1] = mrr[3];
            }
            #pragma unroll
            for (int nf = 0; nf < 4; nf++)
                mma16816(acc[ch][nf], a, bf[nf]);
        }
    }

    // ---- softmax over 1024 cols per row (logit scale 1/8) ----
    const int lr = lane >> 2, lc2 = (lane & 3) * 2;
    const int R0 = g * 16 + lr, R1 = R0 + 8;
    float mx0 = -1e30f, mx1 = -1e30f;
    #pragma unroll
    for (int ch = 0; ch < 8; ch++)
        #pragma unroll
        for (int nf = 0; nf < 4; nf++) {
            #pragma unroll
            for (int p = 0; p < 4; p++) acc[ch][nf][p] *= 0.125f;
            mx0 = fmaxf(mx0, fmaxf(acc[ch][nf][0], acc[ch][nf][1]));
            mx1 = fmaxf(mx1, fmaxf(acc[ch][nf][2], acc[ch][nf][3]));
        }
    mx0 = fmaxf(mx0, __shfl_xor_sync(0xffffffffu, mx0, 1));
    mx0 = fmaxf(mx0, __shfl_xor_sync(0xffffffffu, mx0, 2));
    mx1 = fmaxf(mx1, __shfl_xor_sync(0xffffffffu, mx1, 1));
    mx1 = fmaxf(mx1, __shfl_xor_sync(0xffffffffu, mx1, 2));
    if ((lane & 3) == 0) { redm[R0 * 4 + wc] = mx0; redm[R1 * 4 + wc] = mx1; }
    __syncthreads();                       // all warps done with KV smem too
    // start streaming V while we finish the softmax
    loadT(V, 0, 0); CP_COMMIT();
    loadT(V, 1, 1); CP_COMMIT();

    float M0 = fmaxf(fmaxf(redm[R0*4+0], redm[R0*4+1]), fmaxf(redm[R0*4+2], redm[R0*4+3]));
    float M1 = fmaxf(fmaxf(redm[R1*4+0], redm[R1*4+1]), fmaxf(redm[R1*4+2], redm[R1*4+3]));
    float s0 = 0.f, s1 = 0.f;
    #pragma unroll
    for (int ch = 0; ch < 8; ch++)
        #pragma unroll
        for (int nf = 0; nf < 4; nf++) {
            acc[ch][nf][0] = __expf(acc[ch][nf][0] - M0);
            acc[ch][nf][1] = __expf(acc[ch][nf][1] - M0);
            acc[ch][nf][2] = __expf(acc[ch][nf][2] - M1);
            acc[ch][nf][3] = __expf(acc[ch][nf][3] - M1);
            s0 += acc[ch][nf][0] + acc[ch][nf][1];
            s1 += acc[ch][nf][2] + acc[ch][nf][3];
        }
    s0 += __shfl_xor_sync(0xffffffffu, s0, 1);
    s0 += __shfl_xor_sync(0xffffffffu, s0, 2);
    s1 += __shfl_xor_sync(0xffffffffu, s1, 1);
    s1 += __shfl_xor_sync(0xffffffffu, s1, 2);
    if ((lane & 3) == 0) { reds[R0 * 4 + wc] = s0; reds[R1 * 4 + wc] = s1; }
    __syncthreads();
    float i0 = 1.0f / (reds[R0*4+0] + reds[R0*4+1] + reds[R0*4+2] + reds[R0*4+3]);
    float i1 = 1.0f / (reds[R1*4+0] + reds[R1*4+1] + reds[R1*4+2] + reds[R1*4+3]);

    // normalize in place + write fp32 attention output
    const long base = (long)bh * Ss * Tt;
    float* a0 = attn + base + (long)(m0 + R0) * Tt;
    float* a1 = attn + base + (long)(m0 + R1) * Tt;
    #pragma unroll
    for (int ch = 0; ch < 8; ch++)
        #pragma unroll
        for (int nf = 0; nf < 4; nf++) {
            int col = ch * 128 + wc * 32 + nf * 8 + lc2;
            acc[ch][nf][0] *= i0; acc[ch][nf][1] *= i0;
            acc[ch][nf][2] *= i1; acc[ch][nf][3] *= i1;
            *(float2*)(a0 + col) = make_float2(acc[ch][nf][0], acc[ch][nf][1]);
            *(float2*)(a1 + col) = make_float2(acc[ch][nf][2], acc[ch][nf][3]);
        }

    // ---- P @ V: each warp covers its 256 keys; partial O in registers -----
    float oacc[8][4];
    #pragma unroll
    for (int nb = 0; nb < 8; nb++)
        #pragma unroll
        for (int p = 0; p < 4; p++) oacc[nb][p] = 0.f;

    for (int ch = 0; ch < 8; ch++) {
        CP_WAIT1();
        __syncthreads();
        if (ch + 2 < 8) loadT(V, (ch + 2) % 3, ch + 2);
        CP_COMMIT();
        const int buf = ch % 3;
        #pragma unroll
        for (int ks = 0; ks < 2; ks++) {
            uint32_t a[4];
            a[0] = packh2(acc[ch][2*ks  ][0], acc[ch][2*ks  ][1]);
            a[1] = packh2(acc[ch][2*ks  ][2], acc[ch][2*ks  ][3]);
            a[2] = packh2(acc[ch][2*ks+1][0], acc[ch][2*ks+1][1]);
            a[3] = packh2(acc[ch][2*ks+1][2], acc[ch][2*ks+1][3]);
            #pragma unroll
            for (int p = 0; p < 4; p++) {
                uint32_t mrr[4];
                ldmx4t(mrr, &KV[buf][wc * 32 + ks * 16 + lr16][p * 16 + lk8]);
                uint32_t b0[2] = {mrr[0], mrr[1]};
                uint32_t b1[2] = {mrr[2], mrr[3]};
                mma16816(oacc[2*p],   a, b0);
                mma16816(oacc[2*p+1], a, b1);
            }
        }
    }

    // ---- cross-warp reduction over wc and writeout -------------------------
    #pragma unroll
    for (int nb = 0; nb < 8; nb++) {
        int col = nb * 8 + lc2;
        *(float2*)&Po[(wc * 32 + R0) * 64 + col] = make_float2(oacc[nb][0], oacc[nb][1]);
        *(float2*)&Po[(wc * 32 + R1) * 64 + col] = make_float2(oacc[nb][2], oacc[nb][3]);
    }
    __syncthreads();
    {
        int row = t >> 3, c0 = (t & 7) * 8;
        float o[8];
        #pragma unroll
        for (int j = 0; j < 8; j++)
            o[j] = Po[row * 64 + c0 + j] + Po[(32 + row) * 64 + c0 + j]
                 + Po[(64 + row) * 64 + c0 + j] + Po[(96 + row) * 64 + c0 + j];
        __half* dst = ao + ((long)b * Ss + m0 + row) * Dd + h * 64 + c0;
        __align__(16) __half hh[8];
        #pragma unroll
        for (int j = 0; j < 8; j++) hh[j] = __float2half(o[j]);
        *(uint4*)dst = *(uint4*)hh;
    }
}

// === HMMA fp16 GEMM, 128x256 tile, BK=32 chunks, paired sync (64K/barrier) ==
// 6 chunk buffers = 3 pairs; one __syncthreads per 2 chunks. 512 threads,
// 16 warps in 4x4 grid: each warp 32(M) x 64(N) -> acc[2][8][4] = 64 regs.
template<bool CONV, bool OUTH>
__global__ void __launch_bounds__(512, 1)
gemm256(const __half* __restrict__ A, int lda,
        const __half* __restrict__ B, int ldb,
        void* __restrict__ Cv, int ldc, int K,
        const float* __restrict__ bias,
        const float* __restrict__ res, int relu)
{
    extern __shared__ char dsm[];
    __half (*As)[128][40] = reinterpret_cast<__half(*)[128][40]>(dsm);
    __half (*Bs)[256][40] = reinterpret_cast<__half(*)[256][40]>(dsm + 6 * 128 * 40 * 2);

    const int t = threadIdx.x, lane = t & 31, w = t >> 5;
    const int wm = (w & 3) * 32;     // 4 warps along M
    const int wn = (w >> 2) * 64;    // 4 warps along N
    const int m0 = blockIdx.y * 128, n0 = blockIdx.x * 256;

    // A: 128 rows x 32 halves; 4 threads/row x 8 halves
    const int ar = t >> 2, ac = (t & 3) * 8;
    long abase = 0;
    const __half* agA = A;
    if (CONV) { int m = m0 + ar; abase = (long)((m >> 10) * SP + (m & 1023)); }
    else        agA = A + (long)(m0 + ar) * lda;

    // B: 256 rows x 32 halves; thread covers rows br and br+128
    const int br = t >> 2, bc = (t & 3) * 8;
    const __half* bg0 = B + (long)(n0 + br) * ldb;
    const __half* bg1 = B + (long)(n0 + br + 128) * ldb;

    float acc[2][8][4];
    #pragma unroll
    for (int i = 0; i < 2; i++)
        #pragma unroll
        for (int j = 0; j < 8; j++)
            #pragma unroll
            for (int p = 0; p < 4; p++) acc[i][j][p] = 0.f;

    const int KC2 = K >> 6;   // pairs of BK=32 chunks (all K are multiples of 64)

    auto loadbuf = [&](int buf, int k0) {
        if (CONV) {
            int kk = k0 + ac;
            int kc = kk >> 10, ci = kk & 1023;
            cpa16(&As[buf][ar][ac], A + (abase + kc) * (long)Dd + ci);
        } else {
            cpa16(&As[buf][ar][ac], agA + k0 + ac);
        }
        cpa16(&Bs[buf][br][bc],       bg0 + k0 + bc);
        cpa16(&Bs[buf][br + 128][bc], bg1 + k0 + bc);
    };

    // prologue: pairs 0 and 1 (slots 0 and 1), one commit group per pair
    loadbuf(0, 0);   loadbuf(1, 32);  CP_COMMIT();
    loadbuf(2, 64);  loadbuf(3, 96);  CP_COMMIT();

    const int lr16 = lane & 15;
    const int lk8  = (lane >> 4) * 8;

    for (int c2 = 0; c2 < KC2; ++c2) {
        CP_WAIT1();            // current pair's group complete
        __syncthreads();
        if (c2 + 2 < KC2) {    // prefetch pair c2+2 into slot (c2+2)%3
            int slot = (c2 + 2) % 3;
            int k0 = (c2 + 2) * 64;
            loadbuf(slot * 2, k0);
            loadbuf(slot * 2 + 1, k0 + 32);
        }
        CP_COMMIT();
        const int base = (c2 % 3) * 2;

        #pragma unroll
        for (int half = 0; half < 2; half++) {
            const int buf = base + half;
            #pragma unroll
            for (int ks = 0; ks < 32; ks += 16) {
                uint32_t a[2][4];
                #pragma unroll
                for (int mf = 0; mf < 2; mf++)
                    ldmx4(a[mf], &As[buf][wm + mf * 16 + lr16][ks + lk8]);
                uint32_t bf[8][2];
                #pragma unroll
                for (int p = 0; p < 4; p++) {
                    uint32_t mrr[4];
                    ldmx4(mrr, &Bs[buf][wn + p * 16 + lr16][ks + lk8]);
                    bf[2*p][0]   = mrr[0]; bf[2*p][1]   = mrr[2];
                    bf[2*p+1][0] = mrr[1]; bf[2*p+1][1] = mrr[3];
                }
                #pragma unroll
                for (int mf = 0; mf < 2; mf++)
                    #pragma unroll
                    for (int nf = 0; nf < 8; nf++)
                        mma16816(acc[mf][nf], a[mf], bf[nf]);
            }
        }
    }

    // ---- epilogue ----
    const int lr = lane >> 2;
    const int lc = (lane & 3) * 2;
    #pragma unroll
    for (int mf = 0; mf < 2; mf++) {
        #pragma unroll
        for (int i = 0; i < 2; i++) {
            long mrow = m0 + wm + mf * 16 + lr + i * 8;
            #pragma unroll
            for (int nf = 0; nf < 8; nf++) {
                int col = n0 + wn + nf * 8 + lc;
                float v0 = acc[mf][nf][i * 2 + 0];
                float v1 = acc[mf][nf][i * 2 + 1];
                if (bias) { v0 += bias[col]; v1 += bias[col + 1]; }
                if (res) {
                    float2 rv = *(const float2*)(res + mrow * ldc + col);
                    v0 += rv.x; v1 += rv.y;
                }
                if (relu) { v0 = fmaxf(v0, 0.f); v1 = fmaxf(v1, 0.f); }
                if (OUTH) {
                    *(__half2*)((__half*)Cv + mrow * ldc + col) = __floats2half2_rn(v0, v1);
                } else {
                    *(float2*)((float*)Cv + mrow * ldc + col) = make_float2(v0, v1);
                }
            }
        }
    }
}

// ======================= prep kernels =======================================
struct P8 { const float* p[8]; };
__global__ void cast8(P8 s, __half* __restrict__ d)
{
    long i = ((long)blockIdx.x * 256 + threadIdx.x) * 8;   // over 8*2^20
    int slab = (int)(i >> 20);
    long off = i & 0xFFFFF;
    const float* sp = s.p[slab];
    float4 a = *(const float4*)(sp + off);
    float4 b = *(const float4*)(sp + off + 4);
    __align__(16) __half h[8] = {
        __float2half(a.x), __float2half(a.y), __float2half(a.z), __float2half(a.w),
        __float2half(b.x), __float2half(b.y), __float2half(b.z), __float2half(b.w)};
    *(uint4*)(d + i) = *(uint4*)h;
}

__global__ void cast16(const float* __restrict__ s, __half* __restrict__ d, long n)
{
    long i = ((long)blockIdx.x * 256 + threadIdx.x) * 8;
    if (i >= n) return;
    float4 a = *(const float4*)(s + i);
    float4 b = *(const float4*)(s + i + 4);
    __align__(16) __half h[8] = {
        __float2half(a.x), __float2half(a.y), __float2half(a.z), __float2half(a.w),
        __float2half(b.x), __float2half(b.y), __float2half(b.z), __float2half(b.w)};
    *(uint4*)(d + i) = *(uint4*)h;
}

__global__ void pad_cast(const float* __restrict__ x, __half* __restrict__ xp)
{
    long i = (long)blockIdx.x * 256 + threadIdx.x;   // over Bb*SP*Dd
    int c = (int)(i & 1023);
    long r = i >> 10;
    int b = (int)(r / SP);
    int s = (int)(r - (long)b * SP);
    float val = 0.f;
    if (s >= 4 && s < Ss + 4) val = x[((long)b * Ss + (s - 4)) * Dd + c];
    xp[i] = __float2half(val);
}

// conv1 weight repack via smem transpose: wp[n][kc][ci] = w[n][ci][kc]
__global__ void repack_t(const float* __restrict__ w, __half* __restrict__ wp)
{
    __shared__ float s[9216];
    long n = blockIdx.x;            // 0..DHh-1
    const float* src = w + n * 9216;
    for (int j = threadIdx.x; j < 9216; j += 256) s[j] = src[j];
    __syncthreads();
    __half* dst = wp + n * 9216;
    for (int j = threadIdx.x; j < 9216; j += 256) {
        int kc = j >> 10, ci = j & 1023;
        dst[j] = __float2half(s[ci * 9 + kc]);
    }
}

// merged bias vectors: bqkv = [bq1 | 0 | bv1], bkv = [0 | bv2]
__global__ void build_bias(const float* __restrict__ bq1, const float* __restrict__ bv1,
                           const float* __restrict__ bv2,
                           float* __restrict__ bqkv, float* __restrict__ bkv)
{
    int i = blockIdx.x * 256 + threadIdx.x;   // 0..5119
    if (i < 3072) {
        float v = 0.f;
        if (i < 1024) v = bq1[i];
        else if (i >= 2048) v = bv1[i - 2048];
        bqkv[i] = v;
    } else if (i < 5120) {
        int j = i - 3072;
        bkv[j] = (j < 1024) ? 0.f : bv2[j - 1024];
    }
}

// ======================= launcher ===========================================
extern "C" void kernel_launch(void* const* d_in, const int* in_sizes, int n_in,
                              void* d_out, int out_size)
{
    const float* x    = (const float*)d_in[0];
    const float* xa   = (const float*)d_in[1];
    const float* Wq1  = (const float*)d_in[2];
    const float* bq1  = (const float*)d_in[3];
    const float* Wk1  = (const float*)d_in[4];
    const float* Wv1  = (const float*)d_in[5];
    const float* bv1  = (const float*)d_in[6];
    const float* Wo1  = (const float*)d_in[7];
    const float* bo1  = (const float*)d_in[8];
    const float* gln1 = (const float*)d_in[9];
    const float* bln1 = (const float*)d_in[10];
    const float* Wq2  = (const float*)d_in[11];
    const float* bq2  = (const float*)d_in[12];
    const float* Wk2  = (const float*)d_in[13];
    const float* Wv2  = (const float*)d_in[14];
    const float* bv2  = (const float*)d_in[15];
    const float* Wo2  = (const float*)d_in[16];
    const float* bo2  = (const float*)d_in[17];
    const float* gln2 = (const float*)d_in[18];
    const float* bln2 = (const float*)d_in[19];
    const float* wc1  = (const float*)d_in[20];
    const float* bc1  = (const float*)d_in[21];
    const float* wc2  = (const float*)d_in[22];
    const float* bc2  = (const float*)d_in[23];
    const float* gln3 = (const float*)d_in[24];
    const float* bln3 = (const float*)d_in[25];

    __half *h16, *qkv16, *q2, *kv2, *ao16, *xa16, *xp16, *y16, *wp16, *wc116, *wc216;
    float *px1, *px2, *pz, *pattn, *pbqkv, *pbkv;
    cudaGetSymbolAddress((void**)&h16,   g16_h);
    cudaGetSymbolAddress((void**)&qkv16, g16_qkv);
    cudaGetSymbolAddress((void**)&q2,    g16_q2);
    cudaGetSymbolAddress((void**)&kv2,   g16_kv2);
    cudaGetSymbolAddress((void**)&ao16,  g16_ao);
    cudaGetSymbolAddress((void**)&xa16,  g16_xa);
    cudaGetSymbolAddress((void**)&xp16,  g16_xpad);
    cudaGetSymbolAddress((void**)&y16,   g16_y);
    cudaGetSymbolAddress((void**)&wp16,  g16_wp);
    cudaGetSymbolAddress((void**)&wc116, g16_wc1);
    cudaGetSymbolAddress((void**)&wc216, g16_wc2);
    cudaGetSymbolAddress((void**)&px1,   g_x1);
    cudaGetSymbolAddress((void**)&px2,   g_x2);
    cudaGetSymbolAddress((void**)&pz,    g_z);
    cudaGetSymbolAddress((void**)&pattn, g_attn);
    cudaGetSymbolAddress((void**)&pbqkv, g_bqkv);
    cudaGetSymbolAddress((void**)&pbkv,  g_bkv);

    float* out = (float*)d_out;
    const size_t off1 = (size_t)Bb * Ss * Dd;
    const size_t asz  = (size_t)Bb * Hh * Ss * Tt;
    float* attn1 = pattn;
    float* attn2 = pattn;
    if ((size_t)out_size >= off1 + 2 * asz) {
        attn1 = out + off1;
        attn2 = out + off1 + asz;
    }

    // side stream + events (created once; never during graph capture)
    static cudaStream_t s2 = nullptr;
    static cudaEvent_t evFork = nullptr, evJoin = nullptr;
    if (!s2) {
        cudaStreamCreateWithFlags(&s2, cudaStreamNonBlocking);
        cudaEventCreateWithFlags(&evFork, cudaEventDisableTiming);
        cudaEventCreateWithFlags(&evJoin, cudaEventDisableTiming);
    }

    // dynamic smem opt-in
    constexpr int SM256 = 6 * (128 * 40 + 256 * 40) * 2;    // 184320
    constexpr int SMQK  = 60416 + 32768;                    // 93184
    cudaFuncSetAttribute(gemm256<false,true >, cudaFuncAttributeMaxDynamicSharedMemorySize, SM256);
    cudaFuncSetAttribute(gemm256<false,false>, cudaFuncAttributeMaxDynamicSharedMemorySize, SM256);
    cudaFuncSetAttribute(gemm256<true ,true >, cudaFuncAttributeMaxDynamicSharedMemorySize, SM256);
    cudaFuncSetAttribute(qk_sm_av, cudaFuncAttributeMaxDynamicSharedMemorySize, SMQK);

    const long MM = (long)1024 * 1024;
    dim3 blk(512);
    dim3 gqkv(12, 32);           // N=3072, M=4096
    dim3 gq(4, 32);              // N=1024
    dim3 gkv(8, 32);             // N=2048
    dim3 go(4, 32);              // N=1024
    dim3 gqk(32, Bb * Hh);
    dim3 gc1(8, 32);             // N=2048
    dim3 gc2(4, 32);             // N=1024

    // ---- prep: weight cast (main stream) ----
    P8 ws; ws.p[0]=Wq1; ws.p[1]=Wk1; ws.p[2]=Wv1; ws.p[3]=Wo1;
           ws.p[4]=Wq2; ws.p[5]=Wk2; ws.p[6]=Wv2; ws.p[7]=Wo2;
    cast8<<<4096, 256>>>(ws, wp16);
    build_bias<<<20, 256>>>(bq1, bv1, bv2, pbqkv, pbkv);

    // ---- fork side stream: cross-KV projection + conv-FFN weight prep ----
    cudaEventRecord(evFork, 0);
    cudaStreamWaitEvent(s2, evFork, 0);
    cast16<<<(int)(((long)Bb * Tt * Dd / 8 + 255) / 256), 256, 0, s2>>>(xa, xa16, (long)Bb * Tt * Dd);
    gemm256<false,true><<<gkv, blk, SM256, s2>>>(xa16, Dd, wp16 + 5 * MM, Dd,
        kv2, 2048, Dd, pbkv, nullptr, 0);
    repack_t<<<DHh, 256, 0, s2>>>(wc1, wc116);
    cast16<<<(int)(((long)Dd * DHh / 8 + 255) / 256), 256, 0, s2>>>(wc2, wc216, (long)Dd * DHh);
    cudaEventRecord(evJoin, s2);

    // ---- self attention (main stream) ----
    ln_kernel<true><<<Bb * Ss, 256>>>(x, gln1, bln1, h16);
    gemm256<false,true><<<gqkv, blk, SM256>>>(h16, Dd, wp16, Dd,
        qkv16, 3072, Dd, pbqkv, nullptr, 0);
    qk_sm_av<<<gqk, 256, SMQK>>>(qkv16, 3072, qkv16 + 1024, 3072, attn1, ao16);
    gemm256<false,false><<<go, blk, SM256>>>(ao16, Dd, wp16 + 3 * MM, Dd,
        px1, Dd, Dd, bo1, x, 0);

    // ---- cross attention ----
    ln_kernel<true><<<Bb * Ss, 256>>>(px1, gln2, bln2, h16);
    gemm256<false,true><<<gq, blk, SM256>>>(h16, Dd, wp16 + 4 * MM, Dd,
        q2, 1024, Dd, bq2, nullptr, 0);
    cudaStreamWaitEvent(0, evJoin, 0);   // join: kv2 + conv weights ready
    qk_sm_av<<<gqk, 256, SMQK>>>(q2, 1024, kv2, 2048, attn2, ao16);
    gemm256<false,false><<<go, blk, SM256>>>(ao16, Dd, wp16 + 7 * MM, Dd,
        px2, Dd, Dd, bo2, px1, 0);

    // ---- conv FFN ----
    pad_cast<<<(Bb * SP * Dd) / 256, 256>>>(px2, xp16);
    gemm256<true,true><<<gc1, blk, SM256>>>(xp16, Dd, wc116, 9216,
        y16, DHh, 9216, bc1, nullptr, 1);
    gemm256<false,false><<<gc2, blk, SM256>>>(y16, DHh, wc216, DHh,
        pz, Dd, DHh, bc2, px2, 0);
    ln_kernel<false><<<Bb * Ss, 256>>>(pz, gln3, bln3, out);
}

// round 12
// speedup vs baseline: 1.0477x; 1.0477x over previous
#include <cuda_runtime.h>
#include <cuda_fp16.h>
#include <cstdint>
#include <math.h>

#define Bb 4
#define Ss 1024
#define Tt 1024
#define Dd 1024
#define Hh 16
#define DHh 2048
#define SP 1032   // S + 8 padding rows for conv1

// ======================= scratch ============================================
__device__ __half g16_h   [(size_t)Bb*Ss*Dd];
__device__ __half g16_qkv [(size_t)Bb*Ss*3072];
__device__ __half g16_q2  [(size_t)Bb*Ss*Dd];
__device__ __half g16_kv2 [(size_t)Bb*Ss*2048];
__device__ __half g16_ao  [(size_t)Bb*Ss*Dd];
__device__ __half g16_xa  [(size_t)Bb*Tt*Dd];
__device__ __half g16_xpad[(size_t)Bb*SP*Dd];
__device__ __half g16_y   [(size_t)Bb*Ss*DHh];
__device__ __half g16_wp  [(size_t)8*Dd*Dd];
__device__ __half g16_wc1 [(size_t)DHh*9*Dd];
__device__ __half g16_wc2 [(size_t)Dd*DHh];
__device__ float  g_x1 [Bb*Ss*Dd];
__device__ float  g_x2 [Bb*Ss*Dd];
__device__ float  g_z  [Bb*Ss*Dd];
__device__ float  g_bqkv[3072];
__device__ float  g_bkv [2048];
__device__ float  g_attn[(size_t)Bb*Hh*Ss*Tt];   // fallback if attn not in d_out

// ======================= small PTX helpers ==================================
__device__ __forceinline__ void cpa16(void* s, const void* g) {
    uint32_t sa = (uint32_t)__cvta_generic_to_shared(s);
    asm volatile("cp.async.cg.shared.global [%0], [%1], 16;"
                 :: "r"(sa), "l"(__cvta_generic_to_global(g)));
}
#define CP_COMMIT() asm volatile("cp.async.commit_group;" ::: "memory")
#define CP_WAIT1()  asm volatile("cp.async.wait_group 1;" ::: "memory")

__device__ __forceinline__ void ldmx4(uint32_t* r, const void* p) {
    uint32_t a = (uint32_t)__cvta_generic_to_shared(p);
    asm volatile("ldmatrix.sync.aligned.m8n8.x4.shared.b16 {%0,%1,%2,%3}, [%4];"
                 : "=r"(r[0]), "=r"(r[1]), "=r"(r[2]), "=r"(r[3]) : "r"(a));
}
__device__ __forceinline__ void ldmx4t(uint32_t* r, const void* p) {
    uint32_t a = (uint32_t)__cvta_generic_to_shared(p);
    asm volatile("ldmatrix.sync.aligned.m8n8.x4.trans.shared.b16 {%0,%1,%2,%3}, [%4];"
                 : "=r"(r[0]), "=r"(r[1]), "=r"(r[2]), "=r"(r[3]) : "r"(a));
}
__device__ __forceinline__ void mma16816(float* c, const uint32_t* a, const uint32_t* b) {
    asm volatile("mma.sync.aligned.m16n8k16.row.col.f32.f16.f16.f32 "
                 "{%0,%1,%2,%3}, {%4,%5,%6,%7}, {%8,%9}, {%0,%1,%2,%3};"
                 : "+f"(c[0]), "+f"(c[1]), "+f"(c[2]), "+f"(c[3])
                 : "r"(a[0]), "r"(a[1]), "r"(a[2]), "r"(a[3]),
                   "r"(b[0]), "r"(b[1]));
}
__device__ __forceinline__ uint32_t packh2(float a, float b) {
    __half2 h = __floats2half2_rn(a, b);
    return *(uint32_t*)&h;
}

// ======================= LayerNorm ==========================================
template<bool OUTH>
__global__ void ln_kernel(const float* __restrict__ x,
                          const float* __restrict__ gg,
                          const float* __restrict__ bb,
                          void* __restrict__ outv)
{
    __shared__ float s1[8], s2[8], mv[2];
    long row = blockIdx.x;
    int t = threadIdx.x;
    float4 v = ((const float4*)(x + row * Dd))[t];
    float s = v.x + v.y + v.z + v.w;
    float q = v.x*v.x + v.y*v.y + v.z*v.z + v.w*v.w;
    #pragma unroll
    for (int o = 16; o > 0; o >>= 1) {
        s += __shfl_down_sync(0xffffffffu, s, o);
        q += __shfl_down_sync(0xffffffffu, q, o);
    }
    if ((t & 31) == 0) { s1[t >> 5] = s; s2[t >> 5] = q; }
    __syncthreads();
    if (t == 0) {
        float a = 0.f, c = 0.f;
        #pragma unroll
        for (int i = 0; i < 8; i++) { a += s1[i]; c += s2[i]; }
        float mu  = a * (1.0f / Dd);
        float var = c * (1.0f / Dd) - mu * mu;
        mv[0] = mu; mv[1] = rsqrtf(var + 1e-5f);
    }
    __syncthreads();
    float mu = mv[0], rs = mv[1];
    float4 gv = ((const float4*)gg)[t];
    float4 bv = ((const float4*)bb)[t];
    float o0 = (v.x - mu) * rs * gv.x + bv.x;
    float o1 = (v.y - mu) * rs * gv.y + bv.y;
    float o2 = (v.z - mu) * rs * gv.z + bv.z;
    float o3 = (v.w - mu) * rs * gv.w + bv.w;
    if (OUTH) {
        __align__(8) __half hh[4] = {__float2half(o0), __float2half(o1),
                                     __float2half(o2), __float2half(o3)};
        *(uint2*)((__half*)outv + row * Dd + t * 4) = *(uint2*)hh;
    } else {
        ((float4*)((float*)outv + row * Dd))[t] = make_float4(o0, o1, o2, o3);
    }
}

// ========== Fused QK^T + softmax + P@V (flash-style, 32 q-rows/CTA) =========
// Q rows stride ldq (head offset applied here), K rows stride ldkv, V = K+1024.
// Logits *0.125. Outputs: attn fp32 [bh][S][T], O fp16 into ao[b][s][h*64+dh].
__global__ void __launch_bounds__(256)
qk_sm_av(const __half* __restrict__ qp, int ldq,
         const __half* __restrict__ kvp, int ldkv,
         float* __restrict__ attn, __half* __restrict__ ao)
{
    extern __shared__ char dsm[];
    __half (*Qs)[72] = reinterpret_cast<__half(*)[72]>(dsm);                  // 32x72
    __half (*KV)[128][72] = reinterpret_cast<__half(*)[128][72]>(dsm + 4608); // 3 stages
    float* redm = reinterpret_cast<float*>(dsm + 60416 - 512);                // 32x4
    float* reds = redm + 128;                                                 // 32x4
    float* Po   = reinterpret_cast<float*>(dsm + 60416);                      // 4x32x64

    const int bh = blockIdx.y;
    const int b = bh >> 4, h = bh & 15;
    const __half* Q = qp + (long)b * Ss * ldq + (long)h * 64;
    const __half* K = kvp + (long)b * Ss * ldkv + (long)h * 64;
    const __half* V = K + 1024;
    const int m0 = blockIdx.x * 32;
    const int t = threadIdx.x, lane = t & 31, w = t >> 5;
    const int g = w >> 2, wc = w & 3;

    {
        int r = t >> 3, cc = (t & 7) * 8;
        cpa16(&Qs[r][cc], Q + (long)(m0 + r) * ldq + cc);
    }
    const int ldr = t >> 1, ldc0 = (t & 1) * 32;
    auto loadT = [&](const __half* src0, int buf, int ch) {
        const __half* src = src0 + (long)(ch * 128 + ldr) * ldkv + ldc0;
        cpa16(&KV[buf][ldr][ldc0],      src);
        cpa16(&KV[buf][ldr][ldc0 + 8],  src + 8);
        cpa16(&KV[buf][ldr][ldc0 + 16], src + 16);
        cpa16(&KV[buf][ldr][ldc0 + 24], src + 24);
    };
    loadT(K, 0, 0); CP_COMMIT();
    loadT(K, 1, 1); CP_COMMIT();

    float acc[8][4][4];
    #pragma unroll
    for (int i = 0; i < 8; i++)
        #pragma unroll
        for (int j = 0; j < 4; j++)
            #pragma unroll
            for (int p = 0; p < 4; p++) acc[i][j][p] = 0.f;

    const int lr16 = lane & 15, lk8 = (lane >> 4) * 8;
    for (int ch = 0; ch < 8; ch++) {
        CP_WAIT1();
        __syncthreads();
        if (ch + 2 < 8) loadT(K, (ch + 2) % 3, ch + 2);
        CP_COMMIT();
        const int buf = ch % 3;
        #pragma unroll
        for (int ks = 0; ks < 4; ks++) {
            uint32_t a[4];
            ldmx4(a, &Qs[g * 16 + lr16][ks * 16 + lk8]);
            uint32_t bf[4][2];
            #pragma unroll
            for (int p = 0; p < 2; p++) {
                uint32_t mrr[4];
                ldmx4(mrr, &KV[buf][wc * 32 + p * 16 + lr16][ks * 16 + lk8]);
                bf[2*p][0]   = mrr[0]; bf[2*p][1]   = mrr[2];
                bf[2*p+1][0] = mrr[1]; bf[2*p+1][1] = mrr[3];
            }
            #pragma unroll
            for (int nf = 0; nf < 4; nf++)
                mma16816(acc[ch][nf], a, bf[nf]);
        }
    }

    // ---- softmax over 1024 cols per row (logit scale 1/8) ----
    const int lr = lane >> 2, lc2 = (lane & 3) * 2;
    const int R0 = g * 16 + lr, R1 = R0 + 8;
    float mx0 = -1e30f, mx1 = -1e30f;
    #pragma unroll
    for (int ch = 0; ch < 8; ch++)
        #pragma unroll
        for (int nf = 0; nf < 4; nf++) {
            #pragma unroll
            for (int p = 0; p < 4; p++) acc[ch][nf][p] *= 0.125f;
            mx0 = fmaxf(mx0, fmaxf(acc[ch][nf][0], acc[ch][nf][1]));
            mx1 = fmaxf(mx1, fmaxf(acc[ch][nf][2], acc[ch][nf][3]));
        }
    mx0 = fmaxf(mx0, __shfl_xor_sync(0xffffffffu, mx0, 1));
    mx0 = fmaxf(mx0, __shfl_xor_sync(0xffffffffu, mx0, 2));
    mx1 = fmaxf(mx1, __shfl_xor_sync(0xffffffffu, mx1, 1));
    mx1 = fmaxf(mx1, __shfl_xor_sync(0xffffffffu, mx1, 2));
    if ((lane & 3) == 0) { redm[R0 * 4 + wc] = mx0; redm[R1 * 4 + wc] = mx1; }
    __syncthreads();                       // all warps done with KV smem too
    // start streaming V while we finish the softmax
    loadT(V, 0, 0); CP_COMMIT();
    loadT(V, 1, 1); CP_COMMIT();

    float M0 = fmaxf(fmaxf(redm[R0*4+0], redm[R0*4+1]), fmaxf(redm[R0*4+2], redm[R0*4+3]));
    float M1 = fmaxf(fmaxf(redm[R1*4+0], redm[R1*4+1]), fmaxf(redm[R1*4+2], redm[R1*4+3]));
    float s0 = 0.f, s1 = 0.f;
    #pragma unroll
    for (int ch = 0; ch < 8; ch++)
        #pragma unroll
        for (int nf = 0; nf < 4; nf++) {
            acc[ch][nf][0] = __expf(acc[ch][nf][0] - M0);
            acc[ch][nf][1] = __expf(acc[ch][nf][1] - M0);
            acc[ch][nf][2] = __expf(acc[ch][nf][2] - M1);
            acc[ch][nf][3] = __expf(acc[ch][nf][3] - M1);
            s0 += acc[ch][nf][0] + acc[ch][nf][1];
            s1 += acc[ch][nf][2] + acc[ch][nf][3];
        }
    s0 += __shfl_xor_sync(0xffffffffu, s0, 1);
    s0 += __shfl_xor_sync(0xffffffffu, s0, 2);
    s1 += __shfl_xor_sync(0xffffffffu, s1, 1);
    s1 += __shfl_xor_sync(0xffffffffu, s1, 2);
    if ((lane & 3) == 0) { reds[R0 * 4 + wc] = s0; reds[R1 * 4 + wc] = s1; }
    __syncthreads();
    float i0 = 1.0f / (reds[R0*4+0] + reds[R0*4+1] + reds[R0*4+2] + reds[R0*4+3]);
    float i1 = 1.0f / (reds[R1*4+0] + reds[R1*4+1] + reds[R1*4+2] + reds[R1*4+3]);

    // normalize in place + write fp32 attention output
    const long base = (long)bh * Ss * Tt;
    float* a0 = attn + base + (long)(m0 + R0) * Tt;
    float* a1 = attn + base + (long)(m0 + R1) * Tt;
    #pragma unroll
    for (int ch = 0; ch < 8; ch++)
        #pragma unroll
        for (int nf = 0; nf < 4; nf++) {
            int col = ch * 128 + wc * 32 + nf * 8 + lc2;
            acc[ch][nf][0] *= i0; acc[ch][nf][1] *= i0;
            acc[ch][nf][2] *= i1; acc[ch][nf][3] *= i1;
            *(float2*)(a0 + col) = make_float2(acc[ch][nf][0], acc[ch][nf][1]);
            *(float2*)(a1 + col) = make_float2(acc[ch][nf][2], acc[ch][nf][3]);
        }

    // ---- P @ V: each warp covers its 256 keys; partial O in registers -----
    float oacc[8][4];
    #pragma unroll
    for (int nb = 0; nb < 8; nb++)
        #pragma unroll
        for (int p = 0; p < 4; p++) oacc[nb][p] = 0.f;

    for (int ch = 0; ch < 8; ch++) {
        CP_WAIT1();
        __syncthreads();
        if (ch + 2 < 8) loadT(V, (ch + 2) % 3, ch + 2);
        CP_COMMIT();
        const int buf = ch % 3;
        #pragma unroll
        for (int ks = 0; ks < 2; ks++) {
            uint32_t a[4];
            a[0] = packh2(acc[ch][2*ks  ][0], acc[ch][2*ks  ][1]);
            a[1] = packh2(acc[ch][2*ks  ][2], acc[ch][2*ks  ][3]);
            a[2] = packh2(acc[ch][2*ks+1][0], acc[ch][2*ks+1][1]);
            a[3] = packh2(acc[ch][2*ks+1][2], acc[ch][2*ks+1][3]);
            #pragma unroll
            for (int p = 0; p < 4; p++) {
                uint32_t mrr[4];
                ldmx4t(mrr, &KV[buf][wc * 32 + ks * 16 + lr16][p * 16 + lk8]);
                uint32_t b0[2] = {mrr[0], mrr[1]};
                uint32_t b1[2] = {mrr[2], mrr[3]};
                mma16816(oacc[2*p],   a, b0);
                mma16816(oacc[2*p+1], a, b1);
            }
        }
    }

    // ---- cross-warp reduction over wc and writeout -------------------------
    #pragma unroll
    for (int nb = 0; nb < 8; nb++) {
        int col = nb * 8 + lc2;
        *(float2*)&Po[(wc * 32 + R0) * 64 + col] = make_float2(oacc[nb][0], oacc[nb][1]);
        *(float2*)&Po[(wc * 32 + R1) * 64 + col] = make_float2(oacc[nb][2], oacc[nb][3]);
    }
    __syncthreads();
    {
        int row = t >> 3, c0 = (t & 7) * 8;
        float o[8];
        #pragma unroll
        for (int j = 0; j < 8; j++)
            o[j] = Po[row * 64 + c0 + j] + Po[(32 + row) * 64 + c0 + j]
                 + Po[(64 + row) * 64 + c0 + j] + Po[(96 + row) * 64 + c0 + j];
        __half* dst = ao + ((long)b * Ss + m0 + row) * Dd + h * 64 + c0;
        __align__(16) __half hh[8];
        #pragma unroll
        for (int j = 0; j < 8; j++) hh[j] = __float2half(o[j]);
        *(uint4*)dst = *(uint4*)hh;
    }
}

// ====== HMMA fp16 GEMM, 128x256 tile, BK=32, 3-stage, 512 threads ===========
// (round-9 proven configuration)
template<bool CONV, bool OUTH>
__global__ void __launch_bounds__(512, 1)
gemm256(const __half* __restrict__ A, int lda,
        const __half* __restrict__ B, int ldb,
        void* __restrict__ Cv, int ldc, int K,
        const float* __restrict__ bias,
        const float* __restrict__ res, int relu)
{
    extern __shared__ char dsm[];
    __half (*As)[128][40] = reinterpret_cast<__half(*)[128][40]>(dsm);
    __half (*Bs)[256][40] = reinterpret_cast<__half(*)[256][40]>(dsm + 3 * 128 * 40 * 2);

    const int t = threadIdx.x, lane = t & 31, w = t >> 5;
    const int wm = (w & 3) * 32;     // 4 warps along M
    const int wn = (w >> 2) * 64;    // 4 warps along N
    const int m0 = blockIdx.y * 128, n0 = blockIdx.x * 256;

    const int ar = t >> 2, ac = (t & 3) * 8;
    long abase = 0;
    const __half* agA = A;
    if (CONV) { int m = m0 + ar; abase = (long)((m >> 10) * SP + (m & 1023)); }
    else        agA = A + (long)(m0 + ar) * lda;

    const int br = t >> 2, bc = (t & 3) * 8;
    const __half* bg0 = B + (long)(n0 + br) * ldb;
    const __half* bg1 = B + (long)(n0 + br + 128) * ldb;

    float acc[2][8][4];
    #pragma unroll
    for (int i = 0; i < 2; i++)
        #pragma unroll
        for (int j = 0; j < 8; j++)
            #pragma unroll
            for (int p = 0; p < 4; p++) acc[i][j][p] = 0.f;

    const int KC = K >> 5;   // BK = 32

    auto loadbuf = [&](int buf, int k0) {
        if (CONV) {
            int kk = k0 + ac;
            int kc = kk >> 10, ci = kk & 1023;
            cpa16(&As[buf][ar][ac], A + (abase + kc) * (long)Dd + ci);
        } else {
            cpa16(&As[buf][ar][ac], agA + k0 + ac);
        }
        cpa16(&Bs[buf][br][bc],       bg0 + k0 + bc);
        cpa16(&Bs[buf][br + 128][bc], bg1 + k0 + bc);
    };

    loadbuf(0, 0);  CP_COMMIT();
    loadbuf(1, 32); CP_COMMIT();

    const int lr16 = lane & 15;
    const int lk8  = (lane >> 4) * 8;

    for (int c = 0; c < KC; ++c) {
        CP_WAIT1();
        __syncthreads();
        if (c + 2 < KC) loadbuf((c + 2) % 3, (c + 2) * 32);
        CP_COMMIT();
        const int buf = c % 3;

        #pragma unroll
        for (int ks = 0; ks < 32; ks += 16) {
            uint32_t a[2][4];
            #pragma unroll
            for (int mf = 0; mf < 2; mf++)
                ldmx4(a[mf], &As[buf][wm + mf * 16 + lr16][ks + lk8]);
            uint32_t bf[8][2];
            #pragma unroll
            for (int p = 0; p < 4; p++) {
                uint32_t mrr[4];
                ldmx4(mrr, &Bs[buf][wn + p * 16 + lr16][ks + lk8]);
                bf[2*p][0]   = mrr[0]; bf[2*p][1]   = mrr[2];
                bf[2*p+1][0] = mrr[1]; bf[2*p+1][1] = mrr[3];
            }
            #pragma unroll
            for (int mf = 0; mf < 2; mf++)
                #pragma unroll
                for (int nf = 0; nf < 8; nf++)
                    mma16816(acc[mf][nf], a[mf], bf[nf]);
        }
    }

    // ---- epilogue ----
    const int lr = lane >> 2;
    const int lc = (lane & 3) * 2;
    #pragma unroll
    for (int mf = 0; mf < 2; mf++) {
        #pragma unroll
        for (int i = 0; i < 2; i++) {
            long mrow = m0 + wm + mf * 16 + lr + i * 8;
            #pragma unroll
            for (int nf = 0; nf < 8; nf++) {
                int col = n0 + wn + nf * 8 + lc;
                float v0 = acc[mf][nf][i * 2 + 0];
                float v1 = acc[mf][nf][i * 2 + 1];
                if (bias) { v0 += bias[col]; v1 += bias[col + 1]; }
                if (res) {
                    float2 rv = *(const float2*)(res + mrow * ldc + col);
                    v0 += rv.x; v1 += rv.y;
                }
                if (relu) { v0 = fmaxf(v0, 0.f); v1 = fmaxf(v1, 0.f); }
                if (OUTH) {
                    *(__half2*)((__half*)Cv + mrow * ldc + col) = __floats2half2_rn(v0, v1);
                } else {
                    *(float2*)((float*)Cv + mrow * ldc + col) = make_float2(v0, v1);
                }
            }
        }
    }
}

// ======================= prep kernels =======================================
struct P8 { const float* p[8]; };
// casts nslabs * 2^20 floats; slab j reads s.p[j], writes d + j*2^20
__global__ void castN(P8 s, __half* __restrict__ d)
{
    long i = ((long)blockIdx.x * 256 + threadIdx.x) * 8;
    int slab = (int)(i >> 20);
    long off = i & 0xFFFFF;
    const float* sp = s.p[slab];
    float4 a = *(const float4*)(sp + off);
    float4 b = *(const float4*)(sp + off + 4);
    __align__(16) __half h[8] = {
        __float2half(a.x), __float2half(a.y), __float2half(a.z), __float2half(a.w),
        __float2half(b.x), __float2half(b.y), __float2half(b.z), __float2half(b.w)};
    *(uint4*)(d + i) = *(uint4*)h;
}

__global__ void cast16(const float* __restrict__ s, __half* __restrict__ d, long n)
{
    long i = ((long)blockIdx.x * 256 + threadIdx.x) * 8;
    if (i >= n) return;
    float4 a = *(const float4*)(s + i);
    float4 b = *(const float4*)(s + i + 4);
    __align__(16) __half h[8] = {
        __float2half(a.x), __float2half(a.y), __float2half(a.z), __float2half(a.w),
        __float2half(b.x), __float2half(b.y), __float2half(b.z), __float2half(b.w)};
    *(uint4*)(d + i) = *(uint4*)h;
}

__global__ void pad_cast(const float* __restrict__ x, __half* __restrict__ xp)
{
    long i = (long)blockIdx.x * 256 + threadIdx.x;   // over Bb*SP*Dd
    int c = (int)(i & 1023);
    long r = i >> 10;
    int b = (int)(r / SP);
    int s = (int)(r - (long)b * SP);
    float val = 0.f;
    if (s >= 4 && s < Ss + 4) val = x[((long)b * Ss + (s - 4)) * Dd + c];
    xp[i] = __float2half(val);
}

// conv1 weight repack via smem transpose: wp[n][kc][ci] = w[n][ci][kc]
__global__ void repack_t(const float* __restrict__ w, __half* __restrict__ wp)
{
    __shared__ float s[9216];
    long n = blockIdx.x;            // 0..DHh-1
    const float* src = w + n * 9216;
    for (int j = threadIdx.x; j < 9216; j += 256) s[j] = src[j];
    __syncthreads();
    __half* dst = wp + n * 9216;
    for (int j = threadIdx.x; j < 9216; j += 256) {
        int kc = j >> 10, ci = j & 1023;
        dst[j] = __float2half(s[ci * 9 + kc]);
    }
}

// merged bias vectors: bqkv = [bq1 | 0 | bv1], bkv = [0 | bv2]
__global__ void build_bias(const float* __restrict__ bq1, const float* __restrict__ bv1,
                           const float* __restrict__ bv2,
                           float* __restrict__ bqkv, float* __restrict__ bkv)
{
    int i = blockIdx.x * 256 + threadIdx.x;   // 0..5119
    if (i < 3072) {
        float v = 0.f;
        if (i < 1024) v = bq1[i];
        else if (i >= 2048) v = bv1[i - 2048];
        bqkv[i] = v;
    } else if (i < 5120) {
        int j = i - 3072;
        bkv[j] = (j < 1024) ? 0.f : bv2[j - 1024];
    }
}

// ======================= launcher ===========================================
extern "C" void kernel_launch(void* const* d_in, const int* in_sizes, int n_in,
                              void* d_out, int out_size)
{
    const float* x    = (const float*)d_in[0];
    const float* xa   = (const float*)d_in[1];
    const float* Wq1  = (const float*)d_in[2];
    const float* bq1  = (const float*)d_in[3];
    const float* Wk1  = (const float*)d_in[4];
    const float* Wv1  = (const float*)d_in[5];
    const float* bv1  = (const float*)d_in[6];
    const float* Wo1  = (const float*)d_in[7];
    const float* bo1  = (const float*)d_in[8];
    const float* gln1 = (const float*)d_in[9];
    const float* bln1 = (const float*)d_in[10];
    const float* Wq2  = (const float*)d_in[11];
    const float* bq2  = (const float*)d_in[12];
    const float* Wk2  = (const float*)d_in[13];
    const float* Wv2  = (const float*)d_in[14];
    const float* bv2  = (const float*)d_in[15];
    const float* Wo2  = (const float*)d_in[16];
    const float* bo2  = (const float*)d_in[17];
    const float* gln2 = (const float*)d_in[18];
    const float* bln2 = (const float*)d_in[19];
    const float* wc1  = (const float*)d_in[20];
    const float* bc1  = (const float*)d_in[21];
    const float* wc2  = (const float*)d_in[22];
    const float* bc2  = (const float*)d_in[23];
    const float* gln3 = (const float*)d_in[24];
    const float* bln3 = (const float*)d_in[25];

    __half *h16, *qkv16, *q2, *kv2, *ao16, *xa16, *xp16, *y16, *wp16, *wc116, *wc216;
    float *px1, *px2, *pz, *pattn, *pbqkv, *pbkv;
    cudaGetSymbolAddress((void**)&h16,   g16_h);
    cudaGetSymbolAddress((void**)&qkv16, g16_qkv);
    cudaGetSymbolAddress((void**)&q2,    g16_q2);
    cudaGetSymbolAddress((void**)&kv2,   g16_kv2);
    cudaGetSymbolAddress((void**)&ao16,  g16_ao);
    cudaGetSymbolAddress((void**)&xa16,  g16_xa);
    cudaGetSymbolAddress((void**)&xp16,  g16_xpad);
    cudaGetSymbolAddress((void**)&y16,   g16_y);
    cudaGetSymbolAddress((void**)&wp16,  g16_wp);
    cudaGetSymbolAddress((void**)&wc116, g16_wc1);
    cudaGetSymbolAddress((void**)&wc216, g16_wc2);
    cudaGetSymbolAddress((void**)&px1,   g_x1);
    cudaGetSymbolAddress((void**)&px2,   g_x2);
    cudaGetSymbolAddress((void**)&pz,    g_z);
    cudaGetSymbolAddress((void**)&pattn, g_attn);
    cudaGetSymbolAddress((void**)&pbqkv, g_bqkv);
    cudaGetSymbolAddress((void**)&pbkv,  g_bkv);

    float* out = (float*)d_out;
    const size_t off1 = (size_t)Bb * Ss * Dd;
    const size_t asz  = (size_t)Bb * Hh * Ss * Tt;
    float* attn1 = pattn;
    float* attn2 = pattn;
    if ((size_t)out_size >= off1 + 2 * asz) {
        attn1 = out + off1;
        attn2 = out + off1 + asz;
    }

    // side stream + events (created once; never during graph capture)
    static cudaStream_t s2 = nullptr;
    static cudaEvent_t evFork = nullptr, evJoin = nullptr;
    if (!s2) {
        cudaStreamCreateWithFlags(&s2, cudaStreamNonBlocking);
        cudaEventCreateWithFlags(&evFork, cudaEventDisableTiming);
        cudaEventCreateWithFlags(&evJoin, cudaEventDisableTiming);
    }

    // dynamic smem opt-in
    constexpr int SM256 = 3 * (128 * 40 + 256 * 40) * 2;    // 92160
    constexpr int SMQK  = 60416 + 32768;                    // 93184
    cudaFuncSetAttribute(gemm256<false,true >, cudaFuncAttributeMaxDynamicSharedMemorySize, SM256);
    cudaFuncSetAttribute(gemm256<false,false>, cudaFuncAttributeMaxDynamicSharedMemorySize, SM256);
    cudaFuncSetAttribute(gemm256<true ,true >, cudaFuncAttributeMaxDynamicSharedMemorySize, SM256);
    cudaFuncSetAttribute(qk_sm_av, cudaFuncAttributeMaxDynamicSharedMemorySize, SMQK);

    const long MM = (long)1024 * 1024;
    dim3 blk(512);
    dim3 gqkv(12, 32);           // N=3072, M=4096
    dim3 gq(4, 32);              // N=1024
    dim3 gkv(8, 32);             // N=2048
    dim3 go(4, 32);              // N=1024
    dim3 gqk(32, Bb * Hh);
    dim3 gc1(8, 32);             // N=2048
    dim3 gc2(4, 32);             // N=1024

    // ---- prep: main-stream weight cast (only slabs the main stream uses) ---
    // pool layout: 0..3 = Wq1,Wk1,Wv1,Wo1 | 4 = Wq2 | 5 = Wo2 | 6,7 = Wk2,Wv2
    P8 wsMain; wsMain.p[0]=Wq1; wsMain.p[1]=Wk1; wsMain.p[2]=Wv1;
               wsMain.p[3]=Wo1; wsMain.p[4]=Wq2; wsMain.p[5]=Wo2;
               wsMain.p[6]=Wo2; wsMain.p[7]=Wo2;   // unused
    castN<<<3072, 256>>>(wsMain, wp16);            // slabs 0..5
    build_bias<<<20, 256>>>(bq1, bv1, bv2, pbqkv, pbkv);

    // ---- fork side stream: Wk2/Wv2 cast + cross-KV proj + conv weight prep -
    cudaEventRecord(evFork, 0);
    cudaStreamWaitEvent(s2, evFork, 0);
    P8 wsSide; wsSide.p[0]=Wk2; wsSide.p[1]=Wv2;
               wsSide.p[2]=Wk2; wsSide.p[3]=Wk2; wsSide.p[4]=Wk2;
               wsSide.p[5]=Wk2; wsSide.p[6]=Wk2; wsSide.p[7]=Wk2;  // unused
    castN<<<1024, 256, 0, s2>>>(wsSide, wp16 + 6 * MM);   // slabs 6,7
    cast16<<<(int)(((long)Bb * Tt * Dd / 8 + 255) / 256), 256, 0, s2>>>(xa, xa16, (long)Bb * Tt * Dd);
    gemm256<false,true><<<gkv, blk, SM256, s2>>>(xa16, Dd, wp16 + 6 * MM, Dd,
        kv2, 2048, Dd, pbkv, nullptr, 0);
    repack_t<<<DHh, 256, 0, s2>>>(wc1, wc116);
    cast16<<<(int)(((long)Dd * DHh / 8 + 255) / 256), 256, 0, s2>>>(wc2, wc216, (long)Dd * DHh);
    cudaEventRecord(evJoin, s2);

    // ---- self attention (main stream) ----
    ln_kernel<true><<<Bb * Ss, 256>>>(x, gln1, bln1, h16);
    gemm256<false,true><<<gqkv, blk, SM256>>>(h16, Dd, wp16, Dd,
        qkv16, 3072, Dd, pbqkv, nullptr, 0);
    qk_sm_av<<<gqk, 256, SMQK>>>(qkv16, 3072, qkv16 + 1024, 3072, attn1, ao16);
    gemm256<false,false><<<go, blk, SM256>>>(ao16, Dd, wp16 + 3 * MM, Dd,
        px1, Dd, Dd, bo1, x, 0);

    // ---- cross attention ----
    ln_kernel<true><<<Bb * Ss, 256>>>(px1, gln2, bln2, h16);
    gemm256<false,true><<<gq, blk, SM256>>>(h16, Dd, wp16 + 4 * MM, Dd,
        q2, 1024, Dd, bq2, nullptr, 0);
    cudaStreamWaitEvent(0, evJoin, 0);   // join: kv2 + conv weights ready
    qk_sm_av<<<gqk, 256, SMQK>>>(q2, 1024, kv2, 2048, attn2, ao16);
    gemm256<false,false><<<go, blk, SM256>>>(ao16, Dd, wp16 + 5 * MM, Dd,
        px2, Dd, Dd, bo2, px1, 0);

    // ---- conv FFN ----
    pad_cast<<<(Bb * SP * Dd) / 256, 256>>>(px2, xp16);
    gemm256<true,true><<<gc1, blk, SM256>>>(xp16, Dd, wc116, 9216,
        y16, DHh, 9216, bc1, nullptr, 1);
    gemm256<false,false><<<gc2, blk, SM256>>>(y16, DHh, wc216, DHh,
        pz, Dd, DHh, bc2, px2, 0);
    ln_kernel<false><<<Bb * Ss, 256>>>(pz, gln3, bln3, out);
}

// round 13
// speedup vs baseline: 1.0666x; 1.0180x over previous
#include <cuda_runtime.h>
#include <cuda_fp16.h>
#include <cstdint>
#include <math.h>

#define Bb 4
#define Ss 1024
#define Tt 1024
#define Dd 1024
#define Hh 16
#define DHh 2048
#define SP 1032   // S + 8 padding rows for conv1

// ======================= scratch ============================================
__device__ __half g16_h   [(size_t)Bb*Ss*Dd];
__device__ __half g16_qkv [(size_t)Bb*Ss*3072];
__device__ __half g16_q2  [(size_t)Bb*Ss*Dd];
__device__ __half g16_kv2 [(size_t)Bb*Ss*2048];
__device__ __half g16_ao  [(size_t)Bb*Ss*Dd];
__device__ __half g16_xa  [(size_t)Bb*Tt*Dd];
__device__ __half g16_xpad[(size_t)Bb*SP*Dd];
__device__ __half g16_y   [(size_t)Bb*Ss*DHh];
__device__ __half g16_wp  [(size_t)8*Dd*Dd];
__device__ __half g16_wc1 [(size_t)DHh*9*Dd];
__device__ __half g16_wc2 [(size_t)Dd*DHh];
__device__ float  g_x1 [Bb*Ss*Dd];
__device__ float  g_x2 [Bb*Ss*Dd];
__device__ float  g_z  [Bb*Ss*Dd];
__device__ float  g_bqkv[3072];
__device__ float  g_bkv [2048];
__device__ float  g_attn[(size_t)Bb*Hh*Ss*Tt];   // fallback if attn not in d_out

// ======================= small PTX helpers ==================================
__device__ __forceinline__ void cpa16(void* s, const void* g) {
    uint32_t sa = (uint32_t)__cvta_generic_to_shared(s);
    asm volatile("cp.async.cg.shared.global [%0], [%1], 16;"
                 :: "r"(sa), "l"(__cvta_generic_to_global(g)));
}
#define CP_COMMIT() asm volatile("cp.async.commit_group;" ::: "memory")
#define CP_WAIT1()  asm volatile("cp.async.wait_group 1;" ::: "memory")

__device__ __forceinline__ void ldmx4(uint32_t* r, const void* p) {
    uint32_t a = (uint32_t)__cvta_generic_to_shared(p);
    asm volatile("ldmatrix.sync.aligned.m8n8.x4.shared.b16 {%0,%1,%2,%3}, [%4];"
                 : "=r"(r[0]), "=r"(r[1]), "=r"(r[2]), "=r"(r[3]) : "r"(a));
}
__device__ __forceinline__ void ldmx4t(uint32_t* r, const void* p) {
    uint32_t a = (uint32_t)__cvta_generic_to_shared(p);
    asm volatile("ldmatrix.sync.aligned.m8n8.x4.trans.shared.b16 {%0,%1,%2,%3}, [%4];"
                 : "=r"(r[0]), "=r"(r[1]), "=r"(r[2]), "=r"(r[3]) : "r"(a));
}
__device__ __forceinline__ void mma16816(float* c, const uint32_t* a, const uint32_t* b) {
    asm volatile("mma.sync.aligned.m16n8k16.row.col.f32.f16.f16.f32 "
                 "{%0,%1,%2,%3}, {%4,%5,%6,%7}, {%8,%9}, {%0,%1,%2,%3};"
                 : "+f"(c[0]), "+f"(c[1]), "+f"(c[2]), "+f"(c[3])
                 : "r"(a[0]), "r"(a[1]), "r"(a[2]), "r"(a[3]),
                   "r"(b[0]), "r"(b[1]));
}
__device__ __forceinline__ uint32_t packh2(float a, float b) {
    __half2 h = __floats2half2_rn(a, b);
    return *(uint32_t*)&h;
}
// streaming (write-once) store of float2
__device__ __forceinline__ void stg_cs_f2(float* p, float x, float y) {
    asm volatile("st.global.cs.v2.f32 [%0], {%1, %2};"
                 :: "l"(__cvta_generic_to_global(p)), "f"(x), "f"(y) : "memory");
}

// ======================= LayerNorm ==========================================
template<bool OUTH>
__global__ void ln_kernel(const float* __restrict__ x,
                          const float* __restrict__ gg,
                          const float* __restrict__ bb,
                          void* __restrict__ outv)
{
    __shared__ float s1[8], s2[8], mv[2];
    long row = blockIdx.x;
    int t = threadIdx.x;
    float4 v = ((const float4*)(x + row * Dd))[t];
    float s = v.x + v.y + v.z + v.w;
    float q = v.x*v.x + v.y*v.y + v.z*v.z + v.w*v.w;
    #pragma unroll
    for (int o = 16; o > 0; o >>= 1) {
        s += __shfl_down_sync(0xffffffffu, s, o);
        q += __shfl_down_sync(0xffffffffu, q, o);
    }
    if ((t & 31) == 0) { s1[t >> 5] = s; s2[t >> 5] = q; }
    __syncthreads();
    if (t == 0) {
        float a = 0.f, c = 0.f;
        #pragma unroll
        for (int i = 0; i < 8; i++) { a += s1[i]; c += s2[i]; }
        float mu  = a * (1.0f / Dd);
        float var = c * (1.0f / Dd) - mu * mu;
        mv[0] = mu; mv[1] = rsqrtf(var + 1e-5f);
    }
    __syncthreads();
    float mu = mv[0], rs = mv[1];
    float4 gv = ((const float4*)gg)[t];
    float4 bv = ((const float4*)bb)[t];
    float o0 = (v.x - mu) * rs * gv.x + bv.x;
    float o1 = (v.y - mu) * rs * gv.y + bv.y;
    float o2 = (v.z - mu) * rs * gv.z + bv.z;
    float o3 = (v.w - mu) * rs * gv.w + bv.w;
    if (OUTH) {
        __align__(8) __half hh[4] = {__float2half(o0), __float2half(o1),
                                     __float2half(o2), __float2half(o3)};
        *(uint2*)((__half*)outv + row * Dd + t * 4) = *(uint2*)hh;
    } else {
        ((float4*)((float*)outv + row * Dd))[t] = make_float4(o0, o1, o2, o3);
    }
}

// ========== Fused QK^T + softmax + P@V (flash-style, 32 q-rows/CTA) =========
// Q rows stride ldq (head offset applied here), K rows stride ldkv, V = K+1024.
// Logits *0.125. Outputs: attn fp32 [bh][S][T] (streaming stores),
// O fp16 into ao[b][s][h*64+dh].
__global__ void __launch_bounds__(256)
qk_sm_av(const __half* __restrict__ qp, int ldq,
         const __half* __restrict__ kvp, int ldkv,
         float* __restrict__ attn, __half* __restrict__ ao)
{
    extern __shared__ char dsm[];
    __half (*Qs)[72] = reinterpret_cast<__half(*)[72]>(dsm);                  // 32x72
    __half (*KV)[128][72] = reinterpret_cast<__half(*)[128][72]>(dsm + 4608); // 3 stages
    float* redm = reinterpret_cast<float*>(dsm + 60416 - 512);                // 32x4
    float* reds = redm + 128;                                                 // 32x4
    float* Po   = reinterpret_cast<float*>(dsm + 60416);                      // 4x32x64

    const int bh = blockIdx.y;
    const int b = bh >> 4, h = bh & 15;
    const __half* Q = qp + (long)b * Ss * ldq + (long)h * 64;
    const __half* K = kvp + (long)b * Ss * ldkv + (long)h * 64;
    const __half* V = K + 1024;
    const int m0 = blockIdx.x * 32;
    const int t = threadIdx.x, lane = t & 31, w = t >> 5;
    const int g = w >> 2, wc = w & 3;

    {
        int r = t >> 3, cc = (t & 7) * 8;
        cpa16(&Qs[r][cc], Q + (long)(m0 + r) * ldq + cc);
    }
    const int ldr = t >> 1, ldc0 = (t & 1) * 32;
    auto loadT = [&](const __half* src0, int buf, int ch) {
        const __half* src = src0 + (long)(ch * 128 + ldr) * ldkv + ldc0;
        cpa16(&KV[buf][ldr][ldc0],      src);
        cpa16(&KV[buf][ldr][ldc0 + 8],  src + 8);
        cpa16(&KV[buf][ldr][ldc0 + 16], src + 16);
        cpa16(&KV[buf][ldr][ldc0 + 24], src + 24);
    };
    loadT(K, 0, 0); CP_COMMIT();
    loadT(K, 1, 1); CP_COMMIT();

    float acc[8][4][4];
    #pragma unroll
    for (int i = 0; i < 8; i++)
        #pragma unroll
        for (int j = 0; j < 4; j++)
            #pragma unroll
            for (int p = 0; p < 4; p++) acc[i][j][p] = 0.f;

    const int lr16 = lane & 15, lk8 = (lane >> 4) * 8;
    for (int ch = 0; ch < 8; ch++) {
        CP_WAIT1();
        __syncthreads();
        if (ch + 2 < 8) loadT(K, (ch + 2) % 3, ch + 2);
        CP_COMMIT();
        const int buf = ch % 3;
        #pragma unroll
        for (int ks = 0; ks < 4; ks++) {
            uint32_t a[4];
            ldmx4(a, &Qs[g * 16 + lr16][ks * 16 + lk8]);
            uint32_t bf[4][2];
            #pragma unroll
            for (int p = 0; p < 2; p++) {
                uint32_t mrr[4];
                ldmx4(mrr, &KV[buf][wc * 32 + p * 16 + lr16][ks * 16 + lk8]);
                bf[2*p][0]   = mrr[0]; bf[2*p][1]   = mrr[2];
                bf[2*p+1][0] = mrr[1]; bf[2*p+1][1] = mrr[3];
            }
            #pragma unroll
            for (int nf = 0; nf < 4; nf++)
                mma16816(acc[ch][nf], a, bf[nf]);
        }
    }

    // ---- softmax over 1024 cols per row (logit scale 1/8) ----
    const int lr = lane >> 2, lc2 = (lane & 3) * 2;
    const int R0 = g * 16 + lr, R1 = R0 + 8;
    float mx0 = -1e30f, mx1 = -1e30f;
    #pragma unroll
    for (int ch = 0; ch < 8; ch++)
        #pragma unroll
        for (int nf = 0; nf < 4; nf++) {
            #pragma unroll
            for (int p = 0; p < 4; p++) acc[ch][nf][p] *= 0.125f;
            mx0 = fmaxf(mx0, fmaxf(acc[ch][nf][0], acc[ch][nf][1]));
            mx1 = fmaxf(mx1, fmaxf(acc[ch][nf][2], acc[ch][nf][3]));
        }
    mx0 = fmaxf(mx0, __shfl_xor_sync(0xffffffffu, mx0, 1));
    mx0 = fmaxf(mx0, __shfl_xor_sync(0xffffffffu, mx0, 2));
    mx1 = fmaxf(mx1, __shfl_xor_sync(0xffffffffu, mx1, 1));
    mx1 = fmaxf(mx1, __shfl_xor_sync(0xffffffffu, mx1, 2));
    if ((lane & 3) == 0) { redm[R0 * 4 + wc] = mx0; redm[R1 * 4 + wc] = mx1; }
    __syncthreads();                       // all warps done with KV smem too
    // start streaming V while we finish the softmax
    loadT(V, 0, 0); CP_COMMIT();
    loadT(V, 1, 1); CP_COMMIT();

    float M0 = fmaxf(fmaxf(redm[R0*4+0], redm[R0*4+1]), fmaxf(redm[R0*4+2], redm[R0*4+3]));
    float M1 = fmaxf(fmaxf(redm[R1*4+0], redm[R1*4+1]), fmaxf(redm[R1*4+2], redm[R1*4+3]));
    float s0 = 0.f, s1 = 0.f;
    #pragma unroll
    for (int ch = 0; ch < 8; ch++)
        #pragma unroll
        for (int nf = 0; nf < 4; nf++) {
            acc[ch][nf][0] = __expf(acc[ch][nf][0] - M0);
            acc[ch][nf][1] = __expf(acc[ch][nf][1] - M0);
            acc[ch][nf][2] = __expf(acc[ch][nf][2] - M1);
            acc[ch][nf][3] = __expf(acc[ch][nf][3] - M1);
            s0 += acc[ch][nf][0] + acc[ch][nf][1];
            s1 += acc[ch][nf][2] + acc[ch][nf][3];
        }
    s0 += __shfl_xor_sync(0xffffffffu, s0, 1);
    s0 += __shfl_xor_sync(0xffffffffu, s0, 2);
    s1 += __shfl_xor_sync(0xffffffffu, s1, 1);
    s1 += __shfl_xor_sync(0xffffffffu, s1, 2);
    if ((lane & 3) == 0) { reds[R0 * 4 + wc] = s0; reds[R1 * 4 + wc] = s1; }
    __syncthreads();
    float i0 = 1.0f / (reds[R0*4+0] + reds[R0*4+1] + reds[R0*4+2] + reds[R0*4+3]);
    float i1 = 1.0f / (reds[R1*4+0] + reds[R1*4+1] + reds[R1*4+2] + reds[R1*4+3]);

    // normalize in place + write fp32 attention output (streaming)
    const long base = (long)bh * Ss * Tt;
    float* a0 = attn + base + (long)(m0 + R0) * Tt;
    float* a1 = attn + base + (long)(m0 + R1) * Tt;
    #pragma unroll
    for (int ch = 0; ch < 8; ch++)
        #pragma unroll
        for (int nf = 0; nf < 4; nf++) {
            int col = ch * 128 + wc * 32 + nf * 8 + lc2;
            acc[ch][nf][0] *= i0; acc[ch][nf][1] *= i0;
            acc[ch][nf][2] *= i1; acc[ch][nf][3] *= i1;
            stg_cs_f2(a0 + col, acc[ch][nf][0], acc[ch][nf][1]);
            stg_cs_f2(a1 + col, acc[ch][nf][2], acc[ch][nf][3]);
        }

    // ---- P @ V: each warp covers its 256 keys; partial O in registers -----
    float oacc[8][4];
    #pragma unroll
    for (int nb = 0; nb < 8; nb++)
        #pragma unroll
        for (int p = 0; p < 4; p++) oacc[nb][p] = 0.f;

    for (int ch = 0; ch < 8; ch++) {
        CP_WAIT1();
        __syncthreads();
        if (ch + 2 < 8) loadT(V, (ch + 2) % 3, ch + 2);
        CP_COMMIT();
        const int buf = ch % 3;
        #pragma unroll
        for (int ks = 0; ks < 2; ks++) {
            uint32_t a[4];
            a[0] = packh2(acc[ch][2*ks  ][0], acc[ch][2*ks  ][1]);
            a[1] = packh2(acc[ch][2*ks  ][2], acc[ch][2*ks  ][3]);
            a[2] = packh2(acc[ch][2*ks+1][0], acc[ch][2*ks+1][1]);
            a[3] = packh2(acc[ch][2*ks+1][2], acc[ch][2*ks+1][3]);
            #pragma unroll
            for (int p = 0; p < 4; p++) {
                uint32_t mrr[4];
                ldmx4t(mrr, &KV[buf][wc * 32 + ks * 16 + lr16][p * 16 + lk8]);
                uint32_t b0[2] = {mrr[0], mrr[1]};
                uint32_t b1[2] = {mrr[2], mrr[3]};
                mma16816(oacc[2*p],   a, b0);
                mma16816(oacc[2*p+1], a, b1);
            }
        }
    }

    // ---- cross-warp reduction over wc and writeout -------------------------
    #pragma unroll
    for (int nb = 0; nb < 8; nb++) {
        int col = nb * 8 + lc2;
        *(float2*)&Po[(wc * 32 + R0) * 64 + col] = make_float2(oacc[nb][0], oacc[nb][1]);
        *(float2*)&Po[(wc * 32 + R1) * 64 + col] = make_float2(oacc[nb][2], oacc[nb][3]);
    }
    __syncthreads();
    {
        int row = t >> 3, c0 = (t & 7) * 8;
        float o[8];
        #pragma unroll
        for (int j = 0; j < 8; j++)
            o[j] = Po[row * 64 + c0 + j] + Po[(32 + row) * 64 + c0 + j]
                 + Po[(64 + row) * 64 + c0 + j] + Po[(96 + row) * 64 + c0 + j];
        __half* dst = ao + ((long)b * Ss + m0 + row) * Dd + h * 64 + c0;
        __align__(16) __half hh[8];
        #pragma unroll
        for (int j = 0; j < 8; j++) hh[j] = __float2half(o[j]);
        *(uint4*)dst = *(uint4*)hh;
    }
}

// ====== HMMA fp16 GEMM, 128x256 tile, BK=32, 3-stage, 512 threads ===========
// (round-9 proven configuration; optional fused fp16 padded copy for conv1)
template<bool CONV, bool OUTH>
__global__ void __launch_bounds__(512, 1)
gemm256(const __half* __restrict__ A, int lda,
        const __half* __restrict__ B, int ldb,
        void* __restrict__ Cv, int ldc, int K,
        const float* __restrict__ bias,
        const float* __restrict__ res, int relu,
        __half* __restrict__ xpad)
{
    extern __shared__ char dsm[];
    __half (*As)[128][40] = reinterpret_cast<__half(*)[128][40]>(dsm);
    __half (*Bs)[256][40] = reinterpret_cast<__half(*)[256][40]>(dsm + 3 * 128 * 40 * 2);

    const int t = threadIdx.x, lane = t & 31, w = t >> 5;
    const int wm = (w & 3) * 32;     // 4 warps along M
    const int wn = (w >> 2) * 64;    // 4 warps along N
    const int m0 = blockIdx.y * 128, n0 = blockIdx.x * 256;

    const int ar = t >> 2, ac = (t & 3) * 8;
    long abase = 0;
    const __half* agA = A;
    if (CONV) { int m = m0 + ar; abase = (long)((m >> 10) * SP + (m & 1023)); }
    else        agA = A + (long)(m0 + ar) * lda;

    const int br = t >> 2, bc = (t & 3) * 8;
    const __half* bg0 = B + (long)(n0 + br) * ldb;
    const __half* bg1 = B + (long)(n0 + br + 128) * ldb;

    float acc[2][8][4];
    #pragma unroll
    for (int i = 0; i < 2; i++)
        #pragma unroll
        for (int j = 0; j < 8; j++)
            #pragma unroll
            for (int p = 0; p < 4; p++) acc[i][j][p] = 0.f;

    const int KC = K >> 5;   // BK = 32

    auto loadbuf = [&](int buf, int k0) {
        if (CONV) {
            int kk = k0 + ac;
            int kc = kk >> 10, ci = kk & 1023;
            cpa16(&As[buf][ar][ac], A + (abase + kc) * (long)Dd + ci);
        } else {
            cpa16(&As[buf][ar][ac], agA + k0 + ac);
        }
        cpa16(&Bs[buf][br][bc],       bg0 + k0 + bc);
        cpa16(&Bs[buf][br + 128][bc], bg1 + k0 + bc);
    };

    loadbuf(0, 0);  CP_COMMIT();
    loadbuf(1, 32); CP_COMMIT();

    const int lr16 = lane & 15;
    const int lk8  = (lane >> 4) * 8;

    for (int c = 0; c < KC; ++c) {
        CP_WAIT1();
        __syncthreads();
        if (c + 2 < KC) loadbuf((c + 2) % 3, (c + 2) * 32);
        CP_COMMIT();
        const int buf = c % 3;

        #pragma unroll
        for (int ks = 0; ks < 32; ks += 16) {
            uint32_t a[2][4];
            #pragma unroll
            for (int mf = 0; mf < 2; mf++)
                ldmx4(a[mf], &As[buf][wm + mf * 16 + lr16][ks + lk8]);
            uint32_t bf[8][2];
            #pragma unroll
            for (int p = 0; p < 4; p++) {
                uint32_t mrr[4];
                ldmx4(mrr, &Bs[buf][wn + p * 16 + lr16][ks + lk8]);
                bf[2*p][0]   = mrr[0]; bf[2*p][1]   = mrr[2];
                bf[2*p+1][0] = mrr[1]; bf[2*p+1][1] = mrr[3];
            }
            #pragma unroll
            for (int mf = 0; mf < 2; mf++)
                #pragma unroll
                for (int nf = 0; nf < 8; nf++)
                    mma16816(acc[mf][nf], a[mf], bf[nf]);
        }
    }

    // ---- epilogue ----
    const int lr = lane >> 2;
    const int lc = (lane & 3) * 2;
    #pragma unroll
    for (int mf = 0; mf < 2; mf++) {
        #pragma unroll
        for (int i = 0; i < 2; i++) {
            long mrow = m0 + wm + mf * 16 + lr + i * 8;
            long prow = 0;
            if (xpad) prow = ((mrow >> 10) * SP + (mrow & 1023) + 4) * (long)Dd;
            #pragma unroll
            for (int nf = 0; nf < 8; nf++) {
                int col = n0 + wn + nf * 8 + lc;
                float v0 = acc[mf][nf][i * 2 + 0];
                float v1 = acc[mf][nf][i * 2 + 1];
                if (bias) { v0 += bias[col]; v1 += bias[col + 1]; }
                if (res) {
                    float2 rv = *(const float2*)(res + mrow * ldc + col);
                    v0 += rv.x; v1 += rv.y;
                }
                if (relu) { v0 = fmaxf(v0, 0.f); v1 = fmaxf(v1, 0.f); }
                if (OUTH) {
                    *(__half2*)((__half*)Cv + mrow * ldc + col) = __floats2half2_rn(v0, v1);
                } else {
                    *(float2*)((float*)Cv + mrow * ldc + col) = make_float2(v0, v1);
                }
                if (xpad)
                    *(__half2*)(xpad + prow + col) = __floats2half2_rn(v0, v1);
            }
        }
    }
}

// ======================= prep kernels =======================================
struct P8 { const float* p[8]; };
// casts nslabs * 2^20 floats; slab j reads s.p[j], writes d + j*2^20
__global__ void castN(P8 s, __half* __restrict__ d)
{
    long i = ((long)blockIdx.x * 256 + threadIdx.x) * 8;
    int slab = (int)(i >> 20);
    long off = i & 0xFFFFF;
    const float* sp = s.p[slab];
    float4 a = *(const float4*)(sp + off);
    float4 b = *(const float4*)(sp + off + 4);
    __align__(16) __half h[8] = {
        __float2half(a.x), __float2half(a.y), __float2half(a.z), __float2half(a.w),
        __float2half(b.x), __float2half(b.y), __float2half(b.z), __float2half(b.w)};
    *(uint4*)(d + i) = *(uint4*)h;
}

__global__ void cast16(const float* __restrict__ s, __half* __restrict__ d, long n)
{
    long i = ((long)blockIdx.x * 256 + threadIdx.x) * 8;
    if (i >= n) return;
    float4 a = *(const float4*)(s + i);
    float4 b = *(const float4*)(s + i + 4);
    __align__(16) __half h[8] = {
        __float2half(a.x), __float2half(a.y), __float2half(a.z), __float2half(a.w),
        __float2half(b.x), __float2half(b.y), __float2half(b.z), __float2half(b.w)};
    *(uint4*)(d + i) = *(uint4*)h;
}

// zero the 8 pad rows per batch of xpad (rows 0..3 and 1028..1031 of each SP block)
__global__ void zero_pad(__half* __restrict__ xp)
{
    int i = blockIdx.x * 256 + threadIdx.x;          // 4096 threads, 8 halves each
    long e = (long)i * 8;                            // over [Bb][8][1024]
    int b = (int)(e >> 13);
    int r = (int)((e >> 10) & 7);
    int c = (int)(e & 1023);
    long row = (long)b * SP + (r < 4 ? r : 1024 + r);
    uint4 z = make_uint4(0, 0, 0, 0);
    *(uint4*)(xp + row * Dd + c) = z;
}

// conv1 weight repack via smem transpose: wp[n][kc][ci] = w[n][ci][kc]
__global__ void repack_t(const float* __restrict__ w, __half* __restrict__ wp)
{
    __shared__ float s[9216];
    long n = blockIdx.x;            // 0..DHh-1
    const float* src = w + n * 9216;
    for (int j = threadIdx.x; j < 9216; j += 256) s[j] = src[j];
    __syncthreads();
    __half* dst = wp + n * 9216;
    for (int j = threadIdx.x; j < 9216; j += 256) {
        int kc = j >> 10, ci = j & 1023;
        dst[j] = __float2half(s[ci * 9 + kc]);
    }
}

// merged bias vectors: bqkv = [bq1 | 0 | bv1], bkv = [0 | bv2]
__global__ void build_bias(const float* __restrict__ bq1, const float* __restrict__ bv1,
                           const float* __restrict__ bv2,
                           float* __restrict__ bqkv, float* __restrict__ bkv)
{
    int i = blockIdx.x * 256 + threadIdx.x;   // 0..5119
    if (i < 3072) {
        float v = 0.f;
        if (i < 1024) v = bq1[i];
        else if (i >= 2048) v = bv1[i - 2048];
        bqkv[i] = v;
    } else if (i < 5120) {
        int j = i - 3072;
        bkv[j] = (j < 1024) ? 0.f : bv2[j - 1024];
    }
}

// ======================= launcher ===========================================
extern "C" void kernel_launch(void* const* d_in, const int* in_sizes, int n_in,
                              void* d_out, int out_size)
{
    const float* x    = (const float*)d_in[0];
    const float* xa   = (const float*)d_in[1];
    const float* Wq1  = (const float*)d_in[2];
    const float* bq1  = (const float*)d_in[3];
    const float* Wk1  = (const float*)d_in[4];
    const float* Wv1  = (const float*)d_in[5];
    const float* bv1  = (const float*)d_in[6];
    const float* Wo1  = (const float*)d_in[7];
    const float* bo1  = (const float*)d_in[8];
    const float* gln1 = (const float*)d_in[9];
    const float* bln1 = (const float*)d_in[10];
    const float* Wq2  = (const float*)d_in[11];
    const float* bq2  = (const float*)d_in[12];
    const float* Wk2  = (const float*)d_in[13];
    const float* Wv2  = (const float*)d_in[14];
    const float* bv2  = (const float*)d_in[15];
    const float* Wo2  = (const float*)d_in[16];
    const float* bo2  = (const float*)d_in[17];
    const float* gln2 = (const float*)d_in[18];
    const float* bln2 = (const float*)d_in[19];
    const float* wc1  = (const float*)d_in[20];
    const float* bc1  = (const float*)d_in[21];
    const float* wc2  = (const float*)d_in[22];
    const float* bc2  = (const float*)d_in[23];
    const float* gln3 = (const float*)d_in[24];
    const float* bln3 = (const float*)d_in[25];

    __half *h16, *qkv16, *q2, *kv2, *ao16, *xa16, *xp16, *y16, *wp16, *wc116, *wc216;
    float *px1, *px2, *pz, *pattn, *pbqkv, *pbkv;
    cudaGetSymbolAddress((void**)&h16,   g16_h);
    cudaGetSymbolAddress((void**)&qkv16, g16_qkv);
    cudaGetSymbolAddress((void**)&q2,    g16_q2);
    cudaGetSymbolAddress((void**)&kv2,   g16_kv2);
    cudaGetSymbolAddress((void**)&ao16,  g16_ao);
    cudaGetSymbolAddress((void**)&xa16,  g16_xa);
    cudaGetSymbolAddress((void**)&xp16,  g16_xpad);
    cudaGetSymbolAddress((void**)&y16,   g16_y);
    cudaGetSymbolAddress((void**)&wp16,  g16_wp);
    cudaGetSymbolAddress((void**)&wc116, g16_wc1);
    cudaGetSymbolAddress((void**)&wc216, g16_wc2);
    cudaGetSymbolAddress((void**)&px1,   g_x1);
    cudaGetSymbolAddress((void**)&px2,   g_x2);
    cudaGetSymbolAddress((void**)&pz,    g_z);
    cudaGetSymbolAddress((void**)&pattn, g_attn);
    cudaGetSymbolAddress((void**)&pbqkv, g_bqkv);
    cudaGetSymbolAddress((void**)&pbkv,  g_bkv);

    float* out = (float*)d_out;
    const size_t off1 = (size_t)Bb * Ss * Dd;
    const size_t asz  = (size_t)Bb * Hh * Ss * Tt;
    float* attn1 = pattn;
    float* attn2 = pattn;
    if ((size_t)out_size >= off1 + 2 * asz) {
        attn1 = out + off1;
        attn2 = out + off1 + asz;
    }

    // side stream + events (created once; never during graph capture)
    static cudaStream_t s2 = nullptr;
    static cudaEvent_t evFork = nullptr, evJoin = nullptr;
    if (!s2) {
        cudaStreamCreateWithFlags(&s2, cudaStreamNonBlocking);
        cudaEventCreateWithFlags(&evFork, cudaEventDisableTiming);
        cudaEventCreateWithFlags(&evJoin, cudaEventDisableTiming);
    }

    // dynamic smem opt-in
    constexpr int SM256 = 3 * (128 * 40 + 256 * 40) * 2;    // 92160
    constexpr int SMQK  = 60416 + 32768;                    // 93184
    cudaFuncSetAttribute(gemm256<false,true >, cudaFuncAttributeMaxDynamicSharedMemorySize, SM256);
    cudaFuncSetAttribute(gemm256<false,false>, cudaFuncAttributeMaxDynamicSharedMemorySize, SM256);
    cudaFuncSetAttribute(gemm256<true ,true >, cudaFuncAttributeMaxDynamicSharedMemorySize, SM256);
    cudaFuncSetAttribute(qk_sm_av, cudaFuncAttributeMaxDynamicSharedMemorySize, SMQK);

    const long MM = (long)1024 * 1024;
    dim3 blk(512);
    dim3 gqkv(12, 32);           // N=3072, M=4096
    dim3 gq(4, 32);              // N=1024
    dim3 gkv(8, 32);             // N=2048
    dim3 go(4, 32);              // N=1024
    dim3 gqk(32, Bb * Hh);
    dim3 gc1(8, 32);             // N=2048
    dim3 gc2(4, 32);             // N=1024

    // ---- prep: main-stream weight cast (only slabs the main stream uses) ---
    // pool layout: 0..3 = Wq1,Wk1,Wv1,Wo1 | 4 = Wq2 | 5 = Wo2 | 6,7 = Wk2,Wv2
    P8 wsMain; wsMain.p[0]=Wq1; wsMain.p[1]=Wk1; wsMain.p[2]=Wv1;
               wsMain.p[3]=Wo1; wsMain.p[4]=Wq2; wsMain.p[5]=Wo2;
               wsMain.p[6]=Wo2; wsMain.p[7]=Wo2;   // unused
    castN<<<3072, 256>>>(wsMain, wp16);            // slabs 0..5
    build_bias<<<20, 256>>>(bq1, bv1, bv2, pbqkv, pbkv);

    // ---- fork side stream: Wk2/Wv2 cast + cross-KV proj + conv weight prep -
    cudaEventRecord(evFork, 0);
    cudaStreamWaitEvent(s2, evFork, 0);
    P8 wsSide; wsSide.p[0]=Wk2; wsSide.p[1]=Wv2;
               wsSide.p[2]=Wk2; wsSide.p[3]=Wk2; wsSide.p[4]=Wk2;
               wsSide.p[5]=Wk2; wsSide.p[6]=Wk2; wsSide.p[7]=Wk2;  // unused
    castN<<<1024, 256, 0, s2>>>(wsSide, wp16 + 6 * MM);   // slabs 6,7
    zero_pad<<<16, 256, 0, s2>>>(xp16);
    cast16<<<(int)(((long)Bb * Tt * Dd / 8 + 255) / 256), 256, 0, s2>>>(xa, xa16, (long)Bb * Tt * Dd);
    gemm256<false,true><<<gkv, blk, SM256, s2>>>(xa16, Dd, wp16 + 6 * MM, Dd,
        kv2, 2048, Dd, pbkv, nullptr, 0, nullptr);
    repack_t<<<DHh, 256, 0, s2>>>(wc1, wc116);
    cast16<<<(int)(((long)Dd * DHh / 8 + 255) / 256), 256, 0, s2>>>(wc2, wc216, (long)Dd * DHh);
    cudaEventRecord(evJoin, s2);

    // ---- self attention (main stream) ----
    ln_kernel<true><<<Bb * Ss, 256>>>(x, gln1, bln1, h16);
    gemm256<false,true><<<gqkv, blk, SM256>>>(h16, Dd, wp16, Dd,
        qkv16, 3072, Dd, pbqkv, nullptr, 0, nullptr);
    qk_sm_av<<<gqk, 256, SMQK>>>(qkv16, 3072, qkv16 + 1024, 3072, attn1, ao16);
    gemm256<false,false><<<go, blk, SM256>>>(ao16, Dd, wp16 + 3 * MM, Dd,
        px1, Dd, Dd, bo1, x, 0, nullptr);

    // ---- cross attention ----
    ln_kernel<true><<<Bb * Ss, 256>>>(px1, gln2, bln2, h16);
    gemm256<false,true><<<gq, blk, SM256>>>(h16, Dd, wp16 + 4 * MM, Dd,
        q2, 1024, Dd, bq2, nullptr, 0, nullptr);
    cudaStreamWaitEvent(0, evJoin, 0);   // join: kv2 + conv weights + pad zeros ready
    qk_sm_av<<<gqk, 256, SMQK>>>(q2, 1024, kv2, 2048, attn2, ao16);
    // Wo2 projection: writes px2 fp32 AND fused fp16 padded copy for conv1
    gemm256<false,false><<<go, blk, SM256>>>(ao16, Dd, wp16 + 5 * MM, Dd,
        px2, Dd, Dd, bo2, px1, 0, xp16);

    // ---- conv FFN ----
    gemm256<true,true><<<gc1, blk, SM256>>>(xp16, Dd, wc116, 9216,
        y16, DHh, 9216, bc1, nullptr, 1, nullptr);
    gemm256<false,false><<<gc2, blk, SM256>>>(y16, DHh, wc216, DHh,
        pz, Dd, DHh, bc2, px2, 0, nullptr);
    ln_kernel<false><<<Bb * Ss, 256>>>(pz, gln3, bln3, out);
}